// round 12
// baseline (speedup 1.0000x reference)
#include <cuda_runtime.h>
#include <math.h>

#define N_NODES 100000
#define N_EDGES 1600000
#define F_IN 50
#define NC 32
#define NEG_INF __int_as_float(0xFF800000)

// ---- Scratch (device globals — no allocation allowed) ----
__device__ int   g_csr_src[N_EDGES];
__device__ int   g_deg[N_NODES];
__device__ int   g_rowptr[N_NODES];
__device__ int   g_cursor[N_NODES];
__device__ int   g_excl[N_NODES];
__device__ int   g_bsums[256];
__device__ int   g_is64;
__device__ float g_h1[N_NODES * NC];
__device__ float g_h2[N_NODES * NC];

// ---- Edge dtype detection: one warp, ballot ----
__global__ void detect_dtype_kernel(const int* __restrict__ ei_raw) {
    int lane = threadIdx.x;
    int nz = (ei_raw[2 * lane + 1] != 0) | (ei_raw[2 * (lane + 32) + 1] != 0);
    unsigned any = __ballot_sync(0xffffffff, nz);
    if (lane == 0) g_is64 = (any == 0u);
}

__global__ void zero_deg_kernel(int* __restrict__ deg) {
    int i = blockIdx.x * blockDim.x + threadIdx.x;
    if (i < N_NODES) deg[i] = 0;
}

__global__ void histogram_kernel(const void* __restrict__ ei_raw, int* __restrict__ deg) {
    int i = blockIdx.x * blockDim.x + threadIdx.x;
    if (i >= N_EDGES) return;
    int d;
    if (g_is64) d = (int)((const long long*)ei_raw)[N_EDGES + i];
    else        d = ((const int*)ei_raw)[N_EDGES + i];
    atomicAdd(&deg[d], 1);
}

#define SCAN_BS 512
__global__ void scan_partial_kernel(const int* __restrict__ deg,
                                    int* __restrict__ excl, int* __restrict__ bsums) {
    __shared__ int s[SCAN_BS];
    int i = blockIdx.x * SCAN_BS + threadIdx.x;
    int v = (i < N_NODES) ? deg[i] : 0;
    s[threadIdx.x] = v;
    __syncthreads();
    for (int off = 1; off < SCAN_BS; off <<= 1) {
        int t = (threadIdx.x >= off) ? s[threadIdx.x - off] : 0;
        __syncthreads();
        s[threadIdx.x] += t;
        __syncthreads();
    }
    if (i < N_NODES) excl[i] = s[threadIdx.x] - v;
    if (threadIdx.x == SCAN_BS - 1) bsums[blockIdx.x] = s[SCAN_BS - 1];
}

__global__ void scan_bsums_kernel(int* __restrict__ bsums, int nb) {
    __shared__ int s[256];
    int t = threadIdx.x;
    s[t] = (t < nb) ? bsums[t] : 0;
    __syncthreads();
    if (t == 0) {
        int acc = 0;
        for (int i = 0; i < nb; i++) { int v = s[i]; s[i] = acc; acc += v; }
    }
    __syncthreads();
    if (t < nb) bsums[t] = s[t];
}

__global__ void scan_finish_kernel(const int* __restrict__ excl, const int* __restrict__ bsums,
                                   int* __restrict__ rowptr, int* __restrict__ cursor) {
    int i = blockIdx.x * blockDim.x + threadIdx.x;
    if (i >= N_NODES) return;
    int v = excl[i] + bsums[i / SCAN_BS];
    rowptr[i] = v;
    cursor[i] = v;
}

__global__ void bucket_scatter_kernel(const void* __restrict__ ei_raw,
                                      int* __restrict__ cursor, int* __restrict__ csr_src) {
    int i = blockIdx.x * blockDim.x + threadIdx.x;
    if (i >= N_EDGES) return;
    int s, d;
    if (g_is64) {
        const long long* p = (const long long*)ei_raw;
        s = (int)p[i];
        d = (int)p[N_EDGES + i];
    } else {
        const int* p = (const int*)ei_raw;
        s = p[i];
        d = p[N_EDGES + i];
    }
    int pos = atomicAdd(&cursor[d], 1);
    csr_src[pos] = s;
}

// ---- Layer 1 fused: gather-max (F=50) + linear + ReLU. 4 nodes/block. (R5 structure) ----
__global__ void __launch_bounds__(256)
sage_layer1_kernel(const float* __restrict__ x,
                   const int* __restrict__ rowptr, const int* __restrict__ deg,
                   const int* __restrict__ csr_src,
                   const float* __restrict__ Wl, const float* __restrict__ bl,
                   const float* __restrict__ Wr,
                   float* __restrict__ out) {
    __shared__ float sWl[F_IN][NC];
    __shared__ float sWr[F_IN][NC];
    __shared__ float s_agg[4][F_IN + 2];
    __shared__ float s_part[8][NC];
    int tid = threadIdx.x;
    for (int i = tid; i < F_IN * NC; i += 256) {
        sWl[i / NC][i % NC] = Wl[i];
        sWr[i / NC][i % NC] = Wr[i];
    }

    // Phase 1: gather-max, 64 threads per node, lane f = feature
    int g = tid >> 6;            // 0..3 node slot
    int f = tid & 63;
    int node = blockIdx.x * 4 + g;
    {
        int start = rowptr[node];
        int d = deg[node];
        if (f < F_IN) {
            float v = NEG_INF;
            int j = 0;
            for (; j + 8 <= d; j += 8) {
                int s0 = csr_src[start + j + 0], s1 = csr_src[start + j + 1];
                int s2 = csr_src[start + j + 2], s3 = csr_src[start + j + 3];
                int s4 = csr_src[start + j + 4], s5 = csr_src[start + j + 5];
                int s6 = csr_src[start + j + 6], s7 = csr_src[start + j + 7];
                float a0 = x[s0 * F_IN + f], a1 = x[s1 * F_IN + f];
                float a2 = x[s2 * F_IN + f], a3 = x[s3 * F_IN + f];
                float a4 = x[s4 * F_IN + f], a5 = x[s5 * F_IN + f];
                float a6 = x[s6 * F_IN + f], a7 = x[s7 * F_IN + f];
                v = fmaxf(v, fmaxf(fmaxf(fmaxf(a0, a1), fmaxf(a2, a3)),
                                   fmaxf(fmaxf(a4, a5), fmaxf(a6, a7))));
            }
            for (; j < d; j++) v = fmaxf(v, x[csr_src[start + j] * F_IN + f]);
            s_agg[g][f] = (d == 0) ? 0.0f : v;
        }
    }
    __syncthreads();

    // Phase 2: linear. warp w: node w/2, k-half w&1, lane = col
    int w = tid >> 5;
    int c = tid & 31;
    int nl = w >> 1;
    int r = blockIdx.x * 4 + nl;
    int kbeg = (w & 1) * 25;
    const float* xr = x + r * F_IN;
    float acc = (w & 1) ? 0.0f : bl[c];
#pragma unroll
    for (int k0 = 0; k0 < 25; k0++) {
        int k = kbeg + k0;
        acc += s_agg[nl][k] * sWl[k][c] + xr[k] * sWr[k][c];
    }
    s_part[w][c] = acc;
    __syncthreads();

    if (w < 4) {
        int rr = blockIdx.x * 4 + w;
        float v = s_part[2 * w][c] + s_part[2 * w + 1][c];
        out[rr * NC + c] = fmaxf(v, 0.0f);
    }
}

// ---- Layers 2/3 fused: warp per node, lane = feature.
//      Gather: coalesced index chunk + shfl distribution + predicated tail. ----
template <bool RELU, bool LSM>
__global__ void __launch_bounds__(256)
sage_layer_f32_kernel(const float* __restrict__ hin,
                      const int* __restrict__ rowptr, const int* __restrict__ deg,
                      const int* __restrict__ csr_src,
                      const float* __restrict__ Wl, const float* __restrict__ bl,
                      const float* __restrict__ Wr,
                      float* __restrict__ out) {
    __shared__ float sWl[NC][NC];
    __shared__ float sWr[NC][NC];
    int tid = threadIdx.x;
    for (int i = tid; i < NC * NC; i += 256) {
        sWl[i / NC][i % NC] = Wl[i];
        sWr[i / NC][i % NC] = Wr[i];
    }

    int w = tid >> 5;
    int lane = tid & 31;
    int node = blockIdx.x * 8 + w;

    float bias = bl[lane];
    int start = rowptr[node];
    int d = deg[node];
    float xv = hin[(node << 5) + lane];

    float v = NEG_INF;
    for (int c0 = 0; c0 < d; c0 += 32) {
        int rem = d - c0;                       // > 0, warp-uniform
        int il = min(lane, rem - 1);
        int idxv = csr_src[start + c0 + il];    // ONE coalesced index load per chunk
#pragma unroll
        for (int i = 0; i < 32; i++) {
            if (i < rem) {                      // warp-uniform predicate: no extra loads
                int s = __shfl_sync(0xffffffff, idxv, i);
                v = fmaxf(v, hin[(s << 5) + lane]);
            }
        }
    }
    if (d == 0) v = 0.0f;

    __syncthreads();   // weights ready

    // GEMV: acc_c = sum_k v_k*Wl[k][c] + x_k*Wr[k][c], c = lane
    float acc = bias;
#pragma unroll
    for (int k = 0; k < NC; k++) {
        float vk = __shfl_sync(0xffffffff, v, k);
        float xk = __shfl_sync(0xffffffff, xv, k);
        acc += vk * sWl[k][lane] + xk * sWr[k][lane];
    }

    if (RELU) acc = fmaxf(acc, 0.0f);
    if (LSM) {
        float m = acc;
#pragma unroll
        for (int o = 16; o; o >>= 1) m = fmaxf(m, __shfl_xor_sync(0xffffffff, m, o));
        float ex = __expf(acc - m);
        float s = ex;
#pragma unroll
        for (int o = 16; o; o >>= 1) s += __shfl_xor_sync(0xffffffff, s, o);
        acc = acc - m - __logf(s);
    }
    out[(node << 5) + lane] = acc;
}

extern "C" void kernel_launch(void* const* d_in, const int* in_sizes, int n_in,
                              void* d_out, int out_size) {
    const float* x = (const float*)d_in[0];
    const void* ei = d_in[1];
    const float* Wl1 = (const float*)d_in[2];
    const float* bl1 = (const float*)d_in[3];
    const float* Wr1 = (const float*)d_in[4];
    const float* Wl2 = (const float*)d_in[5];
    const float* bl2 = (const float*)d_in[6];
    const float* Wr2 = (const float*)d_in[7];
    const float* Wl3 = (const float*)d_in[8];
    const float* bl3 = (const float*)d_in[9];
    const float* Wr3 = (const float*)d_in[10];
    float* out = (float*)d_out;

    float *h1, *h2;
    int *csr_src, *deg, *rowptr, *cursor, *excl, *bsums;
    cudaGetSymbolAddress((void**)&h1, g_h1);
    cudaGetSymbolAddress((void**)&h2, g_h2);
    cudaGetSymbolAddress((void**)&csr_src, g_csr_src);
    cudaGetSymbolAddress((void**)&deg, g_deg);
    cudaGetSymbolAddress((void**)&rowptr, g_rowptr);
    cudaGetSymbolAddress((void**)&cursor, g_cursor);
    cudaGetSymbolAddress((void**)&excl, g_excl);
    cudaGetSymbolAddress((void**)&bsums, g_bsums);

    const int eb = (N_EDGES + 255) / 256;
    const int nb = (N_NODES + 255) / 256;
    const int scan_blocks = (N_NODES + SCAN_BS - 1) / SCAN_BS;

    // ---- CSR build directly from raw edge buffer ----
    detect_dtype_kernel<<<1, 32>>>((const int*)ei);
    zero_deg_kernel<<<nb, 256>>>(deg);
    histogram_kernel<<<eb, 256>>>(ei, deg);
    scan_partial_kernel<<<scan_blocks, SCAN_BS>>>(deg, excl, bsums);
    scan_bsums_kernel<<<1, 256>>>(bsums, scan_blocks);
    scan_finish_kernel<<<nb, 256>>>(excl, bsums, rowptr, cursor);
    bucket_scatter_kernel<<<eb, 256>>>(ei, cursor, csr_src);

    // ---- Fused layers ----
    sage_layer1_kernel<<<N_NODES / 4, 256>>>(x, rowptr, deg, csr_src, Wl1, bl1, Wr1, h1);
    sage_layer_f32_kernel<true, false><<<N_NODES / 8, 256>>>(h1, rowptr, deg, csr_src,
                                                             Wl2, bl2, Wr2, h2);
    sage_layer_f32_kernel<false, true><<<N_NODES / 8, 256>>>(h2, rowptr, deg, csr_src,
                                                             Wl3, bl3, Wr3, out);
}

// round 14
// speedup vs baseline: 1.6387x; 1.6387x over previous
#include <cuda_runtime.h>
#include <math.h>

#define N_NODES 100000
#define N_EDGES 1600000
#define F_IN 50
#define NC 32
#define NEG_INF __int_as_float(0xFF800000)

// ---- Scratch (device globals — no allocation allowed) ----
__device__ int   g_csr_src[N_EDGES];
__device__ int   g_deg[N_NODES];
__device__ int   g_rowptr[N_NODES];
__device__ int   g_cursor[N_NODES];
__device__ int   g_excl[N_NODES];
__device__ int   g_bsums[256];
__device__ int   g_is64;
__device__ float g_h1[N_NODES * NC];
__device__ float g_h2[N_NODES * NC];

// ---- Edge dtype detection: one warp, ballot ----
__global__ void detect_dtype_kernel(const int* __restrict__ ei_raw) {
    int lane = threadIdx.x;
    int nz = (ei_raw[2 * lane + 1] != 0) | (ei_raw[2 * (lane + 32) + 1] != 0);
    unsigned any = __ballot_sync(0xffffffff, nz);
    if (lane == 0) g_is64 = (any == 0u);
}

__global__ void zero_deg_kernel(int* __restrict__ deg) {
    int i = blockIdx.x * blockDim.x + threadIdx.x;
    if (i < N_NODES) deg[i] = 0;
}

__global__ void histogram_kernel(const void* __restrict__ ei_raw, int* __restrict__ deg) {
    int i = blockIdx.x * blockDim.x + threadIdx.x;
    if (i >= N_EDGES) return;
    int d;
    if (g_is64) d = (int)((const long long*)ei_raw)[N_EDGES + i];
    else        d = ((const int*)ei_raw)[N_EDGES + i];
    atomicAdd(&deg[d], 1);
}

#define SCAN_BS 512
__global__ void scan_partial_kernel(const int* __restrict__ deg,
                                    int* __restrict__ excl, int* __restrict__ bsums) {
    __shared__ int s[SCAN_BS];
    int i = blockIdx.x * SCAN_BS + threadIdx.x;
    int v = (i < N_NODES) ? deg[i] : 0;
    s[threadIdx.x] = v;
    __syncthreads();
    for (int off = 1; off < SCAN_BS; off <<= 1) {
        int t = (threadIdx.x >= off) ? s[threadIdx.x - off] : 0;
        __syncthreads();
        s[threadIdx.x] += t;
        __syncthreads();
    }
    if (i < N_NODES) excl[i] = s[threadIdx.x] - v;
    if (threadIdx.x == SCAN_BS - 1) bsums[blockIdx.x] = s[SCAN_BS - 1];
}

__global__ void scan_bsums_kernel(int* __restrict__ bsums, int nb) {
    __shared__ int s[256];
    int t = threadIdx.x;
    s[t] = (t < nb) ? bsums[t] : 0;
    __syncthreads();
    if (t == 0) {
        int acc = 0;
        for (int i = 0; i < nb; i++) { int v = s[i]; s[i] = acc; acc += v; }
    }
    __syncthreads();
    if (t < nb) bsums[t] = s[t];
}

__global__ void scan_finish_kernel(const int* __restrict__ excl, const int* __restrict__ bsums,
                                   int* __restrict__ rowptr, int* __restrict__ cursor) {
    int i = blockIdx.x * blockDim.x + threadIdx.x;
    if (i >= N_NODES) return;
    int v = excl[i] + bsums[i / SCAN_BS];
    rowptr[i] = v;
    cursor[i] = v;
}

__global__ void bucket_scatter_kernel(const void* __restrict__ ei_raw,
                                      int* __restrict__ cursor, int* __restrict__ csr_src) {
    int i = blockIdx.x * blockDim.x + threadIdx.x;
    if (i >= N_EDGES) return;
    int s, d;
    if (g_is64) {
        const long long* p = (const long long*)ei_raw;
        s = (int)p[i];
        d = (int)p[N_EDGES + i];
    } else {
        const int* p = (const int*)ei_raw;
        s = p[i];
        d = p[N_EDGES + i];
    }
    int pos = atomicAdd(&cursor[d], 1);
    csr_src[pos] = s;
}

// ---- Layer 1 fused: gather-max (F=50) + linear + ReLU. 4 nodes/block. (exact R5) ----
__global__ void __launch_bounds__(256)
sage_layer1_kernel(const float* __restrict__ x,
                   const int* __restrict__ rowptr, const int* __restrict__ deg,
                   const int* __restrict__ csr_src,
                   const float* __restrict__ Wl, const float* __restrict__ bl,
                   const float* __restrict__ Wr,
                   float* __restrict__ out) {
    __shared__ float sWl[F_IN][NC];
    __shared__ float sWr[F_IN][NC];
    __shared__ float s_agg[4][F_IN + 2];
    __shared__ float s_part[8][NC];
    int tid = threadIdx.x;
    for (int i = tid; i < F_IN * NC; i += 256) {
        sWl[i / NC][i % NC] = Wl[i];
        sWr[i / NC][i % NC] = Wr[i];
    }

    // Phase 1: gather-max, 64 threads per node, lane f = feature
    int g = tid >> 6;            // 0..3 node slot
    int f = tid & 63;
    int node = blockIdx.x * 4 + g;
    {
        int start = rowptr[node];
        int d = deg[node];
        if (f < F_IN) {
            float v = NEG_INF;
            int j = 0;
            for (; j + 8 <= d; j += 8) {
                int s0 = csr_src[start + j + 0], s1 = csr_src[start + j + 1];
                int s2 = csr_src[start + j + 2], s3 = csr_src[start + j + 3];
                int s4 = csr_src[start + j + 4], s5 = csr_src[start + j + 5];
                int s6 = csr_src[start + j + 6], s7 = csr_src[start + j + 7];
                float a0 = x[s0 * F_IN + f], a1 = x[s1 * F_IN + f];
                float a2 = x[s2 * F_IN + f], a3 = x[s3 * F_IN + f];
                float a4 = x[s4 * F_IN + f], a5 = x[s5 * F_IN + f];
                float a6 = x[s6 * F_IN + f], a7 = x[s7 * F_IN + f];
                v = fmaxf(v, fmaxf(fmaxf(fmaxf(a0, a1), fmaxf(a2, a3)),
                                   fmaxf(fmaxf(a4, a5), fmaxf(a6, a7))));
            }
            for (; j < d; j++) v = fmaxf(v, x[csr_src[start + j] * F_IN + f]);
            s_agg[g][f] = (d == 0) ? 0.0f : v;
        }
    }
    __syncthreads();

    // Phase 2: linear. warp w: node w/2, k-half w&1, lane = col
    int w = tid >> 5;
    int c = tid & 31;
    int nl = w >> 1;
    int r = blockIdx.x * 4 + nl;
    int kbeg = (w & 1) * 25;
    const float* xr = x + r * F_IN;
    float acc = (w & 1) ? 0.0f : bl[c];
#pragma unroll
    for (int k0 = 0; k0 < 25; k0++) {
        int k = kbeg + k0;
        acc += s_agg[nl][k] * sWl[k][c] + xr[k] * sWr[k][c];
    }
    s_part[w][c] = acc;
    __syncthreads();

    if (w < 4) {
        int rr = blockIdx.x * 4 + w;
        float v = s_part[2 * w][c] + s_part[2 * w + 1][c];
        out[rr * NC + c] = fmaxf(v, 0.0f);
    }
}

// ---- Layers 2/3 fused: warp per node, lane = feature.
//      Gather: ONE coalesced index load + shfl distribution (full-warp, convergent). ----
template <bool RELU, bool LSM>
__global__ void __launch_bounds__(256)
sage_layer_f32_kernel(const float* __restrict__ hin,
                      const int* __restrict__ rowptr, const int* __restrict__ deg,
                      const int* __restrict__ csr_src,
                      const float* __restrict__ Wl, const float* __restrict__ bl,
                      const float* __restrict__ Wr,
                      float* __restrict__ out) {
    __shared__ float sWl[NC][NC];
    __shared__ float sWr[NC][NC];
    int tid = threadIdx.x;
    for (int i = tid; i < NC * NC; i += 256) {
        sWl[i / NC][i % NC] = Wl[i];
        sWr[i / NC][i % NC] = Wr[i];
    }

    int w = tid >> 5;
    int lane = tid & 31;
    int node = blockIdx.x * 8 + w;

    float bias = bl[lane];
    int start = rowptr[node];
    int d = deg[node];
    float xv = hin[(node << 5) + lane];
    // one coalesced index load per node covers j<32 (all lanes participate)
    int idxreg = (d > 0) ? csr_src[start + min(lane, d - 1)] : 0;

    float v = NEG_INF;
    int j = 0;
    for (; j + 8 <= d && j + 8 <= 32; j += 8) {       // shfl-index fast path
        int s0 = __shfl_sync(0xffffffff, idxreg, j + 0);
        int s1 = __shfl_sync(0xffffffff, idxreg, j + 1);
        int s2 = __shfl_sync(0xffffffff, idxreg, j + 2);
        int s3 = __shfl_sync(0xffffffff, idxreg, j + 3);
        int s4 = __shfl_sync(0xffffffff, idxreg, j + 4);
        int s5 = __shfl_sync(0xffffffff, idxreg, j + 5);
        int s6 = __shfl_sync(0xffffffff, idxreg, j + 6);
        int s7 = __shfl_sync(0xffffffff, idxreg, j + 7);
        float a0 = hin[(s0 << 5) + lane], a1 = hin[(s1 << 5) + lane];
        float a2 = hin[(s2 << 5) + lane], a3 = hin[(s3 << 5) + lane];
        float a4 = hin[(s4 << 5) + lane], a5 = hin[(s5 << 5) + lane];
        float a6 = hin[(s6 << 5) + lane], a7 = hin[(s7 << 5) + lane];
        v = fmaxf(v, fmaxf(fmaxf(fmaxf(a0, a1), fmaxf(a2, a3)),
                           fmaxf(fmaxf(a4, a5), fmaxf(a6, a7))));
    }
    for (; j + 8 <= d; j += 8) {                      // d>32 spillover (rare)
        int s0 = csr_src[start + j + 0], s1 = csr_src[start + j + 1];
        int s2 = csr_src[start + j + 2], s3 = csr_src[start + j + 3];
        int s4 = csr_src[start + j + 4], s5 = csr_src[start + j + 5];
        int s6 = csr_src[start + j + 6], s7 = csr_src[start + j + 7];
        float a0 = hin[(s0 << 5) + lane], a1 = hin[(s1 << 5) + lane];
        float a2 = hin[(s2 << 5) + lane], a3 = hin[(s3 << 5) + lane];
        float a4 = hin[(s4 << 5) + lane], a5 = hin[(s5 << 5) + lane];
        float a6 = hin[(s6 << 5) + lane], a7 = hin[(s7 << 5) + lane];
        v = fmaxf(v, fmaxf(fmaxf(fmaxf(a0, a1), fmaxf(a2, a3)),
                           fmaxf(fmaxf(a4, a5), fmaxf(a6, a7))));
    }
    for (; j < d; j++) {                              // serial tail (warp-uniform j, convergent)
        int s = (j < 32) ? __shfl_sync(0xffffffff, idxreg, j) : csr_src[start + j];
        v = fmaxf(v, hin[(s << 5) + lane]);
    }
    if (d == 0) v = 0.0f;

    __syncthreads();   // weights ready

    // GEMV: acc_c = sum_k v_k*Wl[k][c] + x_k*Wr[k][c], c = lane
    float acc = bias;
#pragma unroll
    for (int k = 0; k < NC; k++) {
        float vk = __shfl_sync(0xffffffff, v, k);
        float xk = __shfl_sync(0xffffffff, xv, k);
        acc += vk * sWl[k][lane] + xk * sWr[k][lane];
    }

    if (RELU) acc = fmaxf(acc, 0.0f);
    if (LSM) {
        float m = acc;
#pragma unroll
        for (int o = 16; o; o >>= 1) m = fmaxf(m, __shfl_xor_sync(0xffffffff, m, o));
        float ex = __expf(acc - m);
        float s = ex;
#pragma unroll
        for (int o = 16; o; o >>= 1) s += __shfl_xor_sync(0xffffffff, s, o);
        acc = acc - m - __logf(s);
    }
    out[(node << 5) + lane] = acc;
}

extern "C" void kernel_launch(void* const* d_in, const int* in_sizes, int n_in,
                              void* d_out, int out_size) {
    const float* x = (const float*)d_in[0];
    const void* ei = d_in[1];
    const float* Wl1 = (const float*)d_in[2];
    const float* bl1 = (const float*)d_in[3];
    const float* Wr1 = (const float*)d_in[4];
    const float* Wl2 = (const float*)d_in[5];
    const float* bl2 = (const float*)d_in[6];
    const float* Wr2 = (const float*)d_in[7];
    const float* Wl3 = (const float*)d_in[8];
    const float* bl3 = (const float*)d_in[9];
    const float* Wr3 = (const float*)d_in[10];
    float* out = (float*)d_out;

    float *h1, *h2;
    int *csr_src, *deg, *rowptr, *cursor, *excl, *bsums;
    cudaGetSymbolAddress((void**)&h1, g_h1);
    cudaGetSymbolAddress((void**)&h2, g_h2);
    cudaGetSymbolAddress((void**)&csr_src, g_csr_src);
    cudaGetSymbolAddress((void**)&deg, g_deg);
    cudaGetSymbolAddress((void**)&rowptr, g_rowptr);
    cudaGetSymbolAddress((void**)&cursor, g_cursor);
    cudaGetSymbolAddress((void**)&excl, g_excl);
    cudaGetSymbolAddress((void**)&bsums, g_bsums);

    const int eb = (N_EDGES + 255) / 256;
    const int nb = (N_NODES + 255) / 256;
    const int scan_blocks = (N_NODES + SCAN_BS - 1) / SCAN_BS;

    // ---- CSR build directly from raw edge buffer ----
    detect_dtype_kernel<<<1, 32>>>((const int*)ei);
    zero_deg_kernel<<<nb, 256>>>(deg);
    histogram_kernel<<<eb, 256>>>(ei, deg);
    scan_partial_kernel<<<scan_blocks, SCAN_BS>>>(deg, excl, bsums);
    scan_bsums_kernel<<<1, 256>>>(bsums, scan_blocks);
    scan_finish_kernel<<<nb, 256>>>(excl, bsums, rowptr, cursor);
    bucket_scatter_kernel<<<eb, 256>>>(ei, cursor, csr_src);

    // ---- Fused layers ----
    sage_layer1_kernel<<<N_NODES / 4, 256>>>(x, rowptr, deg, csr_src, Wl1, bl1, Wr1, h1);
    sage_layer_f32_kernel<true, false><<<N_NODES / 8, 256>>>(h1, rowptr, deg, csr_src,
                                                             Wl2, bl2, Wr2, h2);
    sage_layer_f32_kernel<false, true><<<N_NODES / 8, 256>>>(h2, rowptr, deg, csr_src,
                                                             Wl3, bl3, Wr3, out);
}

// round 15
// speedup vs baseline: 1.7443x; 1.0644x over previous
#include <cuda_runtime.h>
#include <math.h>

#define N_NODES 100000
#define N_EDGES 1600000
#define F_IN 50
#define NC 32
#define NEG_INF __int_as_float(0xFF800000)
#define SCAN_BS 512
#define SCAN_NB 196   // ceil(N_NODES / SCAN_BS)

// ---- Scratch (device globals — no allocation allowed) ----
__device__ int   g_csr_src[N_EDGES];
__device__ int   g_deg[N_NODES];
__device__ int   g_rowptr[N_NODES];
__device__ int   g_cursor[N_NODES];
__device__ int   g_excl[N_NODES];
__device__ int   g_bsums[256];
__device__ int   g_is64;
__device__ float g_h1[N_NODES * NC];
__device__ float g_h2[N_NODES * NC];

// ---- Fused: zero deg + edge dtype detection (block 0, warp 0) ----
__global__ void init_kernel(const int* __restrict__ ei_raw, int* __restrict__ deg) {
    int i = blockIdx.x * blockDim.x + threadIdx.x;
    if (i < N_NODES) deg[i] = 0;
    if (blockIdx.x == 0 && threadIdx.x < 32) {
        int lane = threadIdx.x;
        int nz = (ei_raw[2 * lane + 1] != 0) | (ei_raw[2 * (lane + 32) + 1] != 0);
        unsigned any = __ballot_sync(0xffffffff, nz);
        if (lane == 0) g_is64 = (any == 0u);
    }
}

__global__ void histogram_kernel(const void* __restrict__ ei_raw, int* __restrict__ deg) {
    int i = blockIdx.x * blockDim.x + threadIdx.x;
    if (i >= N_EDGES) return;
    int d;
    if (g_is64) d = (int)((const long long*)ei_raw)[N_EDGES + i];
    else        d = ((const int*)ei_raw)[N_EDGES + i];
    atomicAdd(&deg[d], 1);
}

__global__ void scan_partial_kernel(const int* __restrict__ deg,
                                    int* __restrict__ excl, int* __restrict__ bsums) {
    __shared__ int s[SCAN_BS];
    int i = blockIdx.x * SCAN_BS + threadIdx.x;
    int v = (i < N_NODES) ? deg[i] : 0;
    s[threadIdx.x] = v;
    __syncthreads();
    for (int off = 1; off < SCAN_BS; off <<= 1) {
        int t = (threadIdx.x >= off) ? s[threadIdx.x - off] : 0;
        __syncthreads();
        s[threadIdx.x] += t;
        __syncthreads();
    }
    if (i < N_NODES) excl[i] = s[threadIdx.x] - v;
    if (threadIdx.x == SCAN_BS - 1) bsums[blockIdx.x] = s[SCAN_BS - 1];
}

// ---- Fused: scan the 196 block sums in-block, then finish rowptr/cursor ----
__global__ void scan_finish_kernel(const int* __restrict__ excl, const int* __restrict__ bsums,
                                   int* __restrict__ rowptr, int* __restrict__ cursor) {
    __shared__ int sb[256];
    __shared__ int se[256];
    int t = threadIdx.x;
    int orig = (t < SCAN_NB) ? bsums[t] : 0;
    sb[t] = orig;
    __syncthreads();
    for (int off = 1; off < 256; off <<= 1) {
        int u = (t >= off) ? sb[t - off] : 0;
        __syncthreads();
        sb[t] += u;
        __syncthreads();
    }
    se[t] = sb[t] - orig;       // exclusive prefix of block sums
    __syncthreads();
    int i = blockIdx.x * 256 + t;
    if (i < N_NODES) {
        int v = excl[i] + se[i / SCAN_BS];
        rowptr[i] = v;
        cursor[i] = v;
    }
}

__global__ void bucket_scatter_kernel(const void* __restrict__ ei_raw,
                                      int* __restrict__ cursor, int* __restrict__ csr_src) {
    int i = blockIdx.x * blockDim.x + threadIdx.x;
    if (i >= N_EDGES) return;
    int s, d;
    if (g_is64) {
        const long long* p = (const long long*)ei_raw;
        s = (int)p[i];
        d = (int)p[N_EDGES + i];
    } else {
        const int* p = (const int*)ei_raw;
        s = p[i];
        d = p[N_EDGES + i];
    }
    int pos = atomicAdd(&cursor[d], 1);
    csr_src[pos] = s;
}

// ---- Layer 1 fused: gather-max (F=50) + linear + ReLU. 4 nodes/block. (exact R5) ----
__global__ void __launch_bounds__(256)
sage_layer1_kernel(const float* __restrict__ x,
                   const int* __restrict__ rowptr, const int* __restrict__ deg,
                   const int* __restrict__ csr_src,
                   const float* __restrict__ Wl, const float* __restrict__ bl,
                   const float* __restrict__ Wr,
                   float* __restrict__ out) {
    __shared__ float sWl[F_IN][NC];
    __shared__ float sWr[F_IN][NC];
    __shared__ float s_agg[4][F_IN + 2];
    __shared__ float s_part[8][NC];
    int tid = threadIdx.x;
    for (int i = tid; i < F_IN * NC; i += 256) {
        sWl[i / NC][i % NC] = Wl[i];
        sWr[i / NC][i % NC] = Wr[i];
    }

    // Phase 1: gather-max, 64 threads per node, lane f = feature
    int g = tid >> 6;            // 0..3 node slot
    int f = tid & 63;
    int node = blockIdx.x * 4 + g;
    {
        int start = rowptr[node];
        int d = deg[node];
        if (f < F_IN) {
            float v = NEG_INF;
            int j = 0;
            for (; j + 8 <= d; j += 8) {
                int s0 = csr_src[start + j + 0], s1 = csr_src[start + j + 1];
                int s2 = csr_src[start + j + 2], s3 = csr_src[start + j + 3];
                int s4 = csr_src[start + j + 4], s5 = csr_src[start + j + 5];
                int s6 = csr_src[start + j + 6], s7 = csr_src[start + j + 7];
                float a0 = x[s0 * F_IN + f], a1 = x[s1 * F_IN + f];
                float a2 = x[s2 * F_IN + f], a3 = x[s3 * F_IN + f];
                float a4 = x[s4 * F_IN + f], a5 = x[s5 * F_IN + f];
                float a6 = x[s6 * F_IN + f], a7 = x[s7 * F_IN + f];
                v = fmaxf(v, fmaxf(fmaxf(fmaxf(a0, a1), fmaxf(a2, a3)),
                                   fmaxf(fmaxf(a4, a5), fmaxf(a6, a7))));
            }
            for (; j < d; j++) v = fmaxf(v, x[csr_src[start + j] * F_IN + f]);
            s_agg[g][f] = (d == 0) ? 0.0f : v;
        }
    }
    __syncthreads();

    // Phase 2: linear. warp w: node w/2, k-half w&1, lane = col
    int w = tid >> 5;
    int c = tid & 31;
    int nl = w >> 1;
    int r = blockIdx.x * 4 + nl;
    int kbeg = (w & 1) * 25;
    const float* xr = x + r * F_IN;
    float acc = (w & 1) ? 0.0f : bl[c];
#pragma unroll
    for (int k0 = 0; k0 < 25; k0++) {
        int k = kbeg + k0;
        acc += s_agg[nl][k] * sWl[k][c] + xr[k] * sWr[k][c];
    }
    s_part[w][c] = acc;
    __syncthreads();

    if (w < 4) {
        int rr = blockIdx.x * 4 + w;
        float v = s_part[2 * w][c] + s_part[2 * w + 1][c];
        out[rr * NC + c] = fmaxf(v, 0.0f);
    }
}

// ---- Layers 2/3 fused: warp per node, lane = feature, gather-max + shuffle-GEMV (exact R5) ----
template <bool RELU, bool LSM>
__global__ void __launch_bounds__(256)
sage_layer_f32_kernel(const float* __restrict__ hin,
                      const int* __restrict__ rowptr, const int* __restrict__ deg,
                      const int* __restrict__ csr_src,
                      const float* __restrict__ Wl, const float* __restrict__ bl,
                      const float* __restrict__ Wr,
                      float* __restrict__ out) {
    __shared__ float sWl[NC][NC];
    __shared__ float sWr[NC][NC];
    int tid = threadIdx.x;
    for (int i = tid; i < NC * NC; i += 256) {
        sWl[i / NC][i % NC] = Wl[i];
        sWr[i / NC][i % NC] = Wr[i];
    }

    int w = tid >> 5;
    int lane = tid & 31;
    int node = blockIdx.x * 8 + w;

    float bias = bl[lane];
    int start = rowptr[node];
    int d = deg[node];
    float xv = hin[(node << 5) + lane];

    float v = NEG_INF;
    int j = 0;
    for (; j + 8 <= d; j += 8) {
        int s0 = csr_src[start + j + 0], s1 = csr_src[start + j + 1];
        int s2 = csr_src[start + j + 2], s3 = csr_src[start + j + 3];
        int s4 = csr_src[start + j + 4], s5 = csr_src[start + j + 5];
        int s6 = csr_src[start + j + 6], s7 = csr_src[start + j + 7];
        float a0 = hin[(s0 << 5) + lane], a1 = hin[(s1 << 5) + lane];
        float a2 = hin[(s2 << 5) + lane], a3 = hin[(s3 << 5) + lane];
        float a4 = hin[(s4 << 5) + lane], a5 = hin[(s5 << 5) + lane];
        float a6 = hin[(s6 << 5) + lane], a7 = hin[(s7 << 5) + lane];
        v = fmaxf(v, fmaxf(fmaxf(fmaxf(a0, a1), fmaxf(a2, a3)),
                           fmaxf(fmaxf(a4, a5), fmaxf(a6, a7))));
    }
    for (; j < d; j++) v = fmaxf(v, hin[(csr_src[start + j] << 5) + lane]);
    if (d == 0) v = 0.0f;

    __syncthreads();   // weights ready

    // GEMV: acc_c = sum_k v_k*Wl[k][c] + x_k*Wr[k][c], c = lane
    float acc = bias;
#pragma unroll
    for (int k = 0; k < NC; k++) {
        float vk = __shfl_sync(0xffffffff, v, k);
        float xk = __shfl_sync(0xffffffff, xv, k);
        acc += vk * sWl[k][lane] + xk * sWr[k][lane];
    }

    if (RELU) acc = fmaxf(acc, 0.0f);
    if (LSM) {
        float m = acc;
#pragma unroll
        for (int o = 16; o; o >>= 1) m = fmaxf(m, __shfl_xor_sync(0xffffffff, m, o));
        float ex = __expf(acc - m);
        float s = ex;
#pragma unroll
        for (int o = 16; o; o >>= 1) s += __shfl_xor_sync(0xffffffff, s, o);
        acc = acc - m - __logf(s);
    }
    out[(node << 5) + lane] = acc;
}

extern "C" void kernel_launch(void* const* d_in, const int* in_sizes, int n_in,
                              void* d_out, int out_size) {
    const float* x = (const float*)d_in[0];
    const void* ei = d_in[1];
    const float* Wl1 = (const float*)d_in[2];
    const float* bl1 = (const float*)d_in[3];
    const float* Wr1 = (const float*)d_in[4];
    const float* Wl2 = (const float*)d_in[5];
    const float* bl2 = (const float*)d_in[6];
    const float* Wr2 = (const float*)d_in[7];
    const float* Wl3 = (const float*)d_in[8];
    const float* bl3 = (const float*)d_in[9];
    const float* Wr3 = (const float*)d_in[10];
    float* out = (float*)d_out;

    float *h1, *h2;
    int *csr_src, *deg, *rowptr, *cursor, *excl, *bsums;
    cudaGetSymbolAddress((void**)&h1, g_h1);
    cudaGetSymbolAddress((void**)&h2, g_h2);
    cudaGetSymbolAddress((void**)&csr_src, g_csr_src);
    cudaGetSymbolAddress((void**)&deg, g_deg);
    cudaGetSymbolAddress((void**)&rowptr, g_rowptr);
    cudaGetSymbolAddress((void**)&cursor, g_cursor);
    cudaGetSymbolAddress((void**)&excl, g_excl);
    cudaGetSymbolAddress((void**)&bsums, g_bsums);

    const int eb = (N_EDGES + 255) / 256;
    const int nb = (N_NODES + 255) / 256;

    // ---- CSR build (8 launches total for the whole model) ----
    init_kernel<<<nb, 256>>>((const int*)ei, deg);
    histogram_kernel<<<eb, 256>>>(ei, deg);
    scan_partial_kernel<<<SCAN_NB, SCAN_BS>>>(deg, excl, bsums);
    scan_finish_kernel<<<nb, 256>>>(excl, bsums, rowptr, cursor);
    bucket_scatter_kernel<<<eb, 256>>>(ei, cursor, csr_src);

    // ---- Fused layers (exact R5) ----
    sage_layer1_kernel<<<N_NODES / 4, 256>>>(x, rowptr, deg, csr_src, Wl1, bl1, Wr1, h1);
    sage_layer_f32_kernel<true, false><<<N_NODES / 8, 256>>>(h1, rowptr, deg, csr_src,
                                                             Wl2, bl2, Wr2, h2);
    sage_layer_f32_kernel<false, true><<<N_NODES / 8, 256>>>(h2, rowptr, deg, csr_src,
                                                             Wl3, bl3, Wr3, out);
}

// round 16
// speedup vs baseline: 1.8731x; 1.0738x over previous
#include <cuda_runtime.h>
#include <cuda_fp16.h>
#include <math.h>

#define N_NODES 100000
#define N_EDGES 1600000
#define F_IN 50
#define NHP 25              // half2 pairs per row
#define NC 32
#define NEG_INF __int_as_float(0xFF800000)
#define SCAN_BS 512
#define SCAN_NB 196         // ceil(N_NODES / SCAN_BS)

// ---- Scratch (device globals — no allocation allowed) ----
__device__ int     g_csr_src[N_EDGES];
__device__ int     g_deg[N_NODES];
__device__ int     g_rowptr[N_NODES];
__device__ int     g_cursor[N_NODES];
__device__ int     g_excl[N_NODES];
__device__ int     g_bsums[256];
__device__ int     g_is64;
__device__ __half2 g_xh[N_NODES * NHP];   // fp16 copy of x for the aggregation gather
__device__ float   g_h1[N_NODES * NC];
__device__ float   g_h2[N_NODES * NC];

// ---- Fused: zero deg + edge dtype detection (block 0, warp 0) ----
__global__ void init_kernel(const int* __restrict__ ei_raw, int* __restrict__ deg) {
    int i = blockIdx.x * blockDim.x + threadIdx.x;
    if (i < N_NODES) deg[i] = 0;
    if (blockIdx.x == 0 && threadIdx.x < 32) {
        int lane = threadIdx.x;
        int nz = (ei_raw[2 * lane + 1] != 0) | (ei_raw[2 * (lane + 32) + 1] != 0);
        unsigned any = __ballot_sync(0xffffffff, nz);
        if (lane == 0) g_is64 = (any == 0u);
    }
}

// ---- x -> half2 conversion (one thread per half2 pair; coalesced) ----
__global__ void convert_x_kernel(const float* __restrict__ x, __half2* __restrict__ xh) {
    int i = blockIdx.x * blockDim.x + threadIdx.x;
    if (i >= N_NODES * NHP) return;
    int r = i / NHP, p = i - r * NHP;
    float a = x[r * F_IN + 2 * p];
    float b = x[r * F_IN + 2 * p + 1];
    xh[i] = __floats2half2_rn(a, b);
}

__global__ void histogram_kernel(const void* __restrict__ ei_raw, int* __restrict__ deg) {
    int i = blockIdx.x * blockDim.x + threadIdx.x;
    if (i >= N_EDGES) return;
    int d;
    if (g_is64) d = (int)((const long long*)ei_raw)[N_EDGES + i];
    else        d = ((const int*)ei_raw)[N_EDGES + i];
    atomicAdd(&deg[d], 1);
}

__global__ void scan_partial_kernel(const int* __restrict__ deg,
                                    int* __restrict__ excl, int* __restrict__ bsums) {
    __shared__ int s[SCAN_BS];
    int i = blockIdx.x * SCAN_BS + threadIdx.x;
    int v = (i < N_NODES) ? deg[i] : 0;
    s[threadIdx.x] = v;
    __syncthreads();
    for (int off = 1; off < SCAN_BS; off <<= 1) {
        int t = (threadIdx.x >= off) ? s[threadIdx.x - off] : 0;
        __syncthreads();
        s[threadIdx.x] += t;
        __syncthreads();
    }
    if (i < N_NODES) excl[i] = s[threadIdx.x] - v;
    if (threadIdx.x == SCAN_BS - 1) bsums[blockIdx.x] = s[SCAN_BS - 1];
}

// ---- Fused: scan the 196 block sums in-block, then finish rowptr/cursor ----
__global__ void scan_finish_kernel(const int* __restrict__ excl, const int* __restrict__ bsums,
                                   int* __restrict__ rowptr, int* __restrict__ cursor) {
    __shared__ int sb[256];
    __shared__ int se[256];
    int t = threadIdx.x;
    int orig = (t < SCAN_NB) ? bsums[t] : 0;
    sb[t] = orig;
    __syncthreads();
    for (int off = 1; off < 256; off <<= 1) {
        int u = (t >= off) ? sb[t - off] : 0;
        __syncthreads();
        sb[t] += u;
        __syncthreads();
    }
    se[t] = sb[t] - orig;       // exclusive prefix of block sums
    __syncthreads();
    int i = blockIdx.x * 256 + t;
    if (i < N_NODES) {
        int v = excl[i] + se[i / SCAN_BS];
        rowptr[i] = v;
        cursor[i] = v;
    }
}

__global__ void bucket_scatter_kernel(const void* __restrict__ ei_raw,
                                      int* __restrict__ cursor, int* __restrict__ csr_src) {
    int i = blockIdx.x * blockDim.x + threadIdx.x;
    if (i >= N_EDGES) return;
    int s, d;
    if (g_is64) {
        const long long* p = (const long long*)ei_raw;
        s = (int)p[i];
        d = (int)p[N_EDGES + i];
    } else {
        const int* p = (const int*)ei_raw;
        s = p[i];
        d = p[N_EDGES + i];
    }
    int pos = atomicAdd(&cursor[d], 1);
    csr_src[pos] = s;
}

// ---- Layer 1 fused: warp per node. half2 gather-max (1 warp, 25 lanes) + fp32 shuffle-GEMV + ReLU ----
__global__ void __launch_bounds__(256)
sage_layer1_kernel(const __half2* __restrict__ xh, const float* __restrict__ x,
                   const int* __restrict__ rowptr, const int* __restrict__ deg,
                   const int* __restrict__ csr_src,
                   const float* __restrict__ Wl, const float* __restrict__ bl,
                   const float* __restrict__ Wr,
                   float* __restrict__ out) {
    __shared__ float sWl[F_IN][NC];
    __shared__ float sWr[F_IN][NC];
    int tid = threadIdx.x;
    for (int i = tid; i < F_IN * NC; i += 256) {
        sWl[i / NC][i % NC] = Wl[i];
        sWr[i / NC][i % NC] = Wr[i];
    }

    int w = tid >> 5;
    int lane = tid & 31;
    int node = blockIdx.x * 8 + w;
    int start = rowptr[node];
    int d = deg[node];
    float bias = bl[lane];

    float vx = 0.0f, vy = 0.0f;   // fp32 copies of the aggregated pair (lanes 0..24)
    float xvx = 0.0f, xvy = 0.0f; // self row pair (fp32, exact)
    if (lane < NHP) {
        const float2* xr2 = (const float2*)(x + node * F_IN);  // 8B-aligned: 200B rows
        float2 sv = xr2[lane];
        xvx = sv.x; xvy = sv.y;

        __half2 vm = __floats2half2_rn(NEG_INF, NEG_INF);
        int j = 0;
        for (; j + 8 <= d; j += 8) {
            int s0 = csr_src[start + j + 0], s1 = csr_src[start + j + 1];
            int s2 = csr_src[start + j + 2], s3 = csr_src[start + j + 3];
            int s4 = csr_src[start + j + 4], s5 = csr_src[start + j + 5];
            int s6 = csr_src[start + j + 6], s7 = csr_src[start + j + 7];
            __half2 a0 = xh[s0 * NHP + lane], a1 = xh[s1 * NHP + lane];
            __half2 a2 = xh[s2 * NHP + lane], a3 = xh[s3 * NHP + lane];
            __half2 a4 = xh[s4 * NHP + lane], a5 = xh[s5 * NHP + lane];
            __half2 a6 = xh[s6 * NHP + lane], a7 = xh[s7 * NHP + lane];
            vm = __hmax2(vm, __hmax2(__hmax2(__hmax2(a0, a1), __hmax2(a2, a3)),
                                     __hmax2(__hmax2(a4, a5), __hmax2(a6, a7))));
        }
        for (; j < d; j++) vm = __hmax2(vm, xh[csr_src[start + j] * NHP + lane]);
        float2 vf = __half22float2(vm);
        vx = (d == 0) ? 0.0f : vf.x;
        vy = (d == 0) ? 0.0f : vf.y;
    }
    __syncthreads();   // weights ready; gather lanes converged

    // GEMV: acc_c = sum_k agg_k*Wl[k][c] + x_k*Wr[k][c], c = lane.
    // agg_k / x_k held by lane k>>1, component k&1 (source lanes 0..24; convergent shfl).
    float acc = bias;
#pragma unroll
    for (int k = 0; k < F_IN; k++) {
        float vk = __shfl_sync(0xffffffff, (k & 1) ? vy : vx, k >> 1);
        float xk = __shfl_sync(0xffffffff, (k & 1) ? xvy : xvx, k >> 1);
        acc += vk * sWl[k][lane] + xk * sWr[k][lane];
    }
    out[node * NC + lane] = fmaxf(acc, 0.0f);
}

// ---- Layers 2/3 fused: warp per node, lane = feature, gather-max + shuffle-GEMV (exact R5) ----
template <bool RELU, bool LSM>
__global__ void __launch_bounds__(256)
sage_layer_f32_kernel(const float* __restrict__ hin,
                      const int* __restrict__ rowptr, const int* __restrict__ deg,
                      const int* __restrict__ csr_src,
                      const float* __restrict__ Wl, const float* __restrict__ bl,
                      const float* __restrict__ Wr,
                      float* __restrict__ out) {
    __shared__ float sWl[NC][NC];
    __shared__ float sWr[NC][NC];
    int tid = threadIdx.x;
    for (int i = tid; i < NC * NC; i += 256) {
        sWl[i / NC][i % NC] = Wl[i];
        sWr[i / NC][i % NC] = Wr[i];
    }

    int w = tid >> 5;
    int lane = tid & 31;
    int node = blockIdx.x * 8 + w;

    float bias = bl[lane];
    int start = rowptr[node];
    int d = deg[node];
    float xv = hin[(node << 5) + lane];

    float v = NEG_INF;
    int j = 0;
    for (; j + 8 <= d; j += 8) {
        int s0 = csr_src[start + j + 0], s1 = csr_src[start + j + 1];
        int s2 = csr_src[start + j + 2], s3 = csr_src[start + j + 3];
        int s4 = csr_src[start + j + 4], s5 = csr_src[start + j + 5];
        int s6 = csr_src[start + j + 6], s7 = csr_src[start + j + 7];
        float a0 = hin[(s0 << 5) + lane], a1 = hin[(s1 << 5) + lane];
        float a2 = hin[(s2 << 5) + lane], a3 = hin[(s3 << 5) + lane];
        float a4 = hin[(s4 << 5) + lane], a5 = hin[(s5 << 5) + lane];
        float a6 = hin[(s6 << 5) + lane], a7 = hin[(s7 << 5) + lane];
        v = fmaxf(v, fmaxf(fmaxf(fmaxf(a0, a1), fmaxf(a2, a3)),
                           fmaxf(fmaxf(a4, a5), fmaxf(a6, a7))));
    }
    for (; j < d; j++) v = fmaxf(v, hin[(csr_src[start + j] << 5) + lane]);
    if (d == 0) v = 0.0f;

    __syncthreads();   // weights ready

    float acc = bias;
#pragma unroll
    for (int k = 0; k < NC; k++) {
        float vk = __shfl_sync(0xffffffff, v, k);
        float xk = __shfl_sync(0xffffffff, xv, k);
        acc += vk * sWl[k][lane] + xk * sWr[k][lane];
    }

    if (RELU) acc = fmaxf(acc, 0.0f);
    if (LSM) {
        float m = acc;
#pragma unroll
        for (int o = 16; o; o >>= 1) m = fmaxf(m, __shfl_xor_sync(0xffffffff, m, o));
        float ex = __expf(acc - m);
        float s = ex;
#pragma unroll
        for (int o = 16; o; o >>= 1) s += __shfl_xor_sync(0xffffffff, s, o);
        acc = acc - m - __logf(s);
    }
    out[(node << 5) + lane] = acc;
}

extern "C" void kernel_launch(void* const* d_in, const int* in_sizes, int n_in,
                              void* d_out, int out_size) {
    const float* x = (const float*)d_in[0];
    const void* ei = d_in[1];
    const float* Wl1 = (const float*)d_in[2];
    const float* bl1 = (const float*)d_in[3];
    const float* Wr1 = (const float*)d_in[4];
    const float* Wl2 = (const float*)d_in[5];
    const float* bl2 = (const float*)d_in[6];
    const float* Wr2 = (const float*)d_in[7];
    const float* Wl3 = (const float*)d_in[8];
    const float* bl3 = (const float*)d_in[9];
    const float* Wr3 = (const float*)d_in[10];
    float* out = (float*)d_out;

    float *h1, *h2;
    __half2* xh;
    int *csr_src, *deg, *rowptr, *cursor, *excl, *bsums;
    cudaGetSymbolAddress((void**)&h1, g_h1);
    cudaGetSymbolAddress((void**)&h2, g_h2);
    cudaGetSymbolAddress((void**)&xh, g_xh);
    cudaGetSymbolAddress((void**)&csr_src, g_csr_src);
    cudaGetSymbolAddress((void**)&deg, g_deg);
    cudaGetSymbolAddress((void**)&rowptr, g_rowptr);
    cudaGetSymbolAddress((void**)&cursor, g_cursor);
    cudaGetSymbolAddress((void**)&excl, g_excl);
    cudaGetSymbolAddress((void**)&bsums, g_bsums);

    const int eb = (N_EDGES + 255) / 256;
    const int nb = (N_NODES + 255) / 256;

    // ---- CSR build + fp16 conversion ----
    init_kernel<<<nb, 256>>>((const int*)ei, deg);
    convert_x_kernel<<<(N_NODES * NHP + 255) / 256, 256>>>(x, xh);
    histogram_kernel<<<eb, 256>>>(ei, deg);
    scan_partial_kernel<<<SCAN_NB, SCAN_BS>>>(deg, excl, bsums);
    scan_finish_kernel<<<nb, 256>>>(excl, bsums, rowptr, cursor);
    bucket_scatter_kernel<<<eb, 256>>>(ei, cursor, csr_src);

    // ---- Fused layers ----
    sage_layer1_kernel<<<N_NODES / 8, 256>>>(xh, x, rowptr, deg, csr_src, Wl1, bl1, Wr1, h1);
    sage_layer_f32_kernel<true, false><<<N_NODES / 8, 256>>>(h1, rowptr, deg, csr_src,
                                                             Wl2, bl2, Wr2, h2);
    sage_layer_f32_kernel<false, true><<<N_NODES / 8, 256>>>(h2, rowptr, deg, csr_src,
                                                             Wl3, bl3, Wr3, out);
}